// round 16
// baseline (speedup 1.0000x reference)
#include <cuda_runtime.h>
#include <cuda_bf16.h>
#include <cstdint>

// MaxUnpooling2D scatter-add.
//   updates/mask: [B=16, H=128, W=128, C=64]  -> 16,777,216 elements
//   output:       [B=16, OH=256, OW=256, C=64] -> 67,108,864 floats (268 MB)
// out_idx = (b<<22) | (mask & ~63) | c   (channel comes from the source element)
//
// R16: combine the two mechanisms that individually won / held ground:
//   - GROUP=2 kernel sizes (R6: 2048-block scatter, 8192-block zero -- grids
//     big enough to fill the chip; per-kernel working set 33.5MB L2-resident)
//   - two capture-forked streams (R15: cross-stream HW backfill covers each
//     pipeline's zero->scatter boundary tails without role interleave)
// Stream A: groups {0,2,4,6}; stream B: groups {1,3,5,7}. Unfused
// zero(g);scatter(g) per group -- stream order gives the only real dependency.

static constexpr int B_DIM     = 16;
static constexpr int GROUP     = 2;
static constexpr int NGROUPS   = B_DIM / GROUP;       // 8
static constexpr int HWC       = 1 << 20;             // elems per batch
static constexpr int OUT_PER_B = 1 << 22;             // out floats per batch
static constexpr int THREADS   = 256;

static constexpr int SQ_PER_G  = GROUP * HWC / 4;     // 524,288 quads per group
static constexpr int S_BLOCKS  = SQ_PER_G / THREADS;  // 2048
static constexpr int ZV_PER_G  = GROUP * OUT_PER_B / 4; // 2,097,152 float4 per group
static constexpr int Z_BLOCKS  = ZV_PER_G / THREADS;  // 8192

// ---------------------------------------------------------------------------
__global__ void __launch_bounds__(THREADS)
zero_kernel(float4* __restrict__ out4)
{
    out4[blockIdx.x * THREADS + threadIdx.x] = make_float4(0.f, 0.f, 0.f, 0.f);
}

__global__ void __launch_bounds__(THREADS)
scatter_kernel(const float4* __restrict__ upd4,
               const int4*   __restrict__ msk4,
               float* __restrict__ out_g)
{
    int q  = blockIdx.x * THREADS + threadIdx.x;  // quad index in group
    int bl = q >> 18;                             // batch within group
    int c  = (q << 2) & 63;                       // channel of first lane

    float4 u = __ldg(&upd4[q]);
    int4   m = __ldg(&msk4[q]);

    int base = bl << 22;
    atomicAdd(&out_g[base | (m.x & ~63) | (c + 0)], u.x);
    atomicAdd(&out_g[base | (m.y & ~63) | (c + 1)], u.y);
    atomicAdd(&out_g[base | (m.z & ~63) | (c + 2)], u.z);
    atomicAdd(&out_g[base | (m.w & ~63) | (c + 3)], u.w);
}

// ---------------------------------------------------------------------------
extern "C" void kernel_launch(void* const* d_in, const int* in_sizes, int n_in,
                              void* d_out, int out_size)
{
    const float4* upd4 = (const float4*)d_in[0];
    const int4*   msk4 = (const int4*)d_in[1];
    float*        out  = (float*)d_out;

    // Host-side stream/event objects, created once (no device memory).
    static cudaStream_t s2 = nullptr;
    static cudaEvent_t  ev_fork = nullptr, ev_join = nullptr;
    if (s2 == nullptr) {
        cudaStreamCreateWithFlags(&s2, cudaStreamNonBlocking);
        cudaEventCreateWithFlags(&ev_fork, cudaEventDisableTiming);
        cudaEventCreateWithFlags(&ev_join, cudaEventDisableTiming);
    }

    // Fork s2 into the capture, dependent on capture-stream head.
    cudaEventRecord(ev_fork, 0);
    cudaStreamWaitEvent(s2, ev_fork, 0);

    const size_t GRP_QUADS = (size_t)SQ_PER_G;
    const size_t GRP_OUT   = (size_t)GROUP * OUT_PER_B;

    // Two pipelines: even groups on stream 0, odd groups on s2.
    for (int g = 0; g < NGROUPS; g++) {
        cudaStream_t st = (g & 1) ? s2 : (cudaStream_t)0;
        float* out_g = out + (size_t)g * GRP_OUT;

        zero_kernel<<<Z_BLOCKS, THREADS, 0, st>>>((float4*)out_g);
        scatter_kernel<<<S_BLOCKS, THREADS, 0, st>>>(
            upd4 + (size_t)g * GRP_QUADS,
            msk4 + (size_t)g * GRP_QUADS,
            out_g);
    }

    // Join.
    cudaEventRecord(ev_join, s2);
    cudaStreamWaitEvent((cudaStream_t)0, ev_join, 0);
}